// round 1
// baseline (speedup 1.0000x reference)
#include <cuda_runtime.h>

#define TT 1024
#define BB 4
#define DIM 1024
#define NH 16
#define HD 64
#define NTOK (TT * BB)     // 4096 tokens
#define ROWSTR (BB * DIM)  // 4096 floats per t-step

// ---------------- scratch (device globals; no allocations allowed) --------
__device__ float g_q[NTOK * DIM];
__device__ float g_k[NTOK * DIM];
__device__ float g_v[NTOK * DIM];
__device__ float g_ctx[NTOK * DIM];
__device__ float g_t1[NTOK * DIM];
__device__ float g_h[NTOK * DIM];
__device__ float g_t2[NTOK * DIM];

// ===========================================================================
// SGEMM: C[4096,1024] = A[4096,1024] @ W[1024,1024]^T + bias
// Both A and W are K-contiguous (row-major, K innermost) -> "NT" layout.
// 128x128 tile, BK=16, 256 threads, 8x8 per-thread micro-tile.
// ===========================================================================
__global__ __launch_bounds__(256, 2)
void gemm_nt_bias(const float* __restrict__ A, const float* __restrict__ W,
                  const float* __restrict__ bias, float* __restrict__ C) {
    __shared__ float As[16][132];  // [k][m], padded: 132*4B keeps 16B alignment
    __shared__ float Bs[16][132];  // [k][n]

    const int tid = threadIdx.x;
    const int tx = tid & 15;       // n-direction
    const int ty = tid >> 4;       // m-direction
    const int m0 = blockIdx.y * 128;
    const int n0 = blockIdx.x * 128;

    // loader mapping: 128 rows x 16 k per tile; each thread: 2 rows x 1 float4
    const int lr = tid >> 2;            // 0..63
    const int lc = (tid & 3) << 2;      // 0,4,8,12

    const float* Ap = A + (size_t)(m0 + lr) * DIM + lc;
    const float* Wp = W + (size_t)(n0 + lr) * DIM + lc;

    float acc[8][8];
#pragma unroll
    for (int i = 0; i < 8; i++)
#pragma unroll
        for (int j = 0; j < 8; j++) acc[i][j] = 0.f;

    for (int k0 = 0; k0 < DIM; k0 += 16) {
        float4 a0 = *(const float4*)(Ap + k0);
        float4 a1 = *(const float4*)(Ap + (size_t)64 * DIM + k0);
        float4 b0 = *(const float4*)(Wp + k0);
        float4 b1 = *(const float4*)(Wp + (size_t)64 * DIM + k0);
        __syncthreads();  // previous iteration's compute done
        As[lc + 0][lr] = a0.x; As[lc + 1][lr] = a0.y;
        As[lc + 2][lr] = a0.z; As[lc + 3][lr] = a0.w;
        As[lc + 0][lr + 64] = a1.x; As[lc + 1][lr + 64] = a1.y;
        As[lc + 2][lr + 64] = a1.z; As[lc + 3][lr + 64] = a1.w;
        Bs[lc + 0][lr] = b0.x; Bs[lc + 1][lr] = b0.y;
        Bs[lc + 2][lr] = b0.z; Bs[lc + 3][lr] = b0.w;
        Bs[lc + 0][lr + 64] = b1.x; Bs[lc + 1][lr + 64] = b1.y;
        Bs[lc + 2][lr + 64] = b1.z; Bs[lc + 3][lr + 64] = b1.w;
        __syncthreads();
#pragma unroll
        for (int kk = 0; kk < 16; kk++) {
            float4 a04 = *(const float4*)(&As[kk][ty * 8]);
            float4 a14 = *(const float4*)(&As[kk][ty * 8 + 4]);
            float4 b04 = *(const float4*)(&Bs[kk][tx * 8]);
            float4 b14 = *(const float4*)(&Bs[kk][tx * 8 + 4]);
            float ar[8] = {a04.x, a04.y, a04.z, a04.w, a14.x, a14.y, a14.z, a14.w};
            float br[8] = {b04.x, b04.y, b04.z, b04.w, b14.x, b14.y, b14.z, b14.w};
#pragma unroll
            for (int i = 0; i < 8; i++)
#pragma unroll
                for (int j = 0; j < 8; j++)
                    acc[i][j] = fmaf(ar[i], br[j], acc[i][j]);
        }
    }

    float4 bv0 = *(const float4*)(bias + n0 + tx * 8);
    float4 bv1 = *(const float4*)(bias + n0 + tx * 8 + 4);
#pragma unroll
    for (int i = 0; i < 8; i++) {
        float* Cp = C + (size_t)(m0 + ty * 8 + i) * DIM + n0 + tx * 8;
        float4 c0 = make_float4(acc[i][0] + bv0.x, acc[i][1] + bv0.y,
                                acc[i][2] + bv0.z, acc[i][3] + bv0.w);
        float4 c1 = make_float4(acc[i][4] + bv1.x, acc[i][5] + bv1.y,
                                acc[i][6] + bv1.z, acc[i][7] + bv1.w);
        *(float4*)Cp = c0;
        *(float4*)(Cp + 4) = c1;
    }
}

// ===========================================================================
// Flash-style full attention, fp32.
// grid: (B*H = 64, T/64 = 16); block 256 threads (16x16), 4x4 micro-tile.
// smem: Qs[64][68], Ks[64][68] (reused to hold P), Vs[64][68]  -> 52224 B
// ===========================================================================
#define LDPAD 68
#define ATT_SMEM (3 * 64 * LDPAD * 4)

__global__ __launch_bounds__(256, 2)
void attn_kernel(const float* __restrict__ q, const float* __restrict__ k,
                 const float* __restrict__ v, float* __restrict__ ctx) {
    extern __shared__ float sm[];
    float* Qs = sm;                   // [64][LDPAD]
    float* Ks = sm + 64 * LDPAD;      // [64][LDPAD], reused for P
    float* Vs = sm + 2 * 64 * LDPAD;  // [64][LDPAD]

    const int tid = threadIdx.x;
    const int tx = tid & 15;  // s-cols of S / d-cols of O
    const int ty = tid >> 4;  // query rows
    const int b = blockIdx.x >> 4;
    const int h = blockIdx.x & 15;
    const int t0 = blockIdx.y * 64;
    const size_t base = (size_t)b * DIM + h * HD;

    // load Q tile [64 x 64]
#pragma unroll
    for (int i = 0; i < 4; i++) {
        int idx = tid + i * 256;
        int r = idx >> 4, c = (idx & 15) << 2;
        *(float4*)(Qs + r * LDPAD + c) =
            *(const float4*)(q + (size_t)(t0 + r) * ROWSTR + base + c);
    }

    float o[4][4];
#pragma unroll
    for (int i = 0; i < 4; i++)
#pragma unroll
        for (int j = 0; j < 4; j++) o[i][j] = 0.f;
    float mr[4] = {-1e30f, -1e30f, -1e30f, -1e30f};
    float lsum[4] = {0.f, 0.f, 0.f, 0.f};

    for (int s0 = 0; s0 < TT; s0 += 64) {
        __syncthreads();  // prior P@V finished before K/V overwrite
#pragma unroll
        for (int i = 0; i < 4; i++) {
            int idx = tid + i * 256;
            int r = idx >> 4, c = (idx & 15) << 2;
            *(float4*)(Ks + r * LDPAD + c) =
                *(const float4*)(k + (size_t)(s0 + r) * ROWSTR + base + c);
            *(float4*)(Vs + r * LDPAD + c) =
                *(const float4*)(v + (size_t)(s0 + r) * ROWSTR + base + c);
        }
        __syncthreads();

        // S = Q K^T (4x4 per thread), over d = 0..63
        float s[4][4];
#pragma unroll
        for (int i = 0; i < 4; i++)
#pragma unroll
            for (int j = 0; j < 4; j++) s[i][j] = 0.f;
#pragma unroll
        for (int d4 = 0; d4 < 16; d4++) {
            float4 qv[4], kv[4];
#pragma unroll
            for (int i = 0; i < 4; i++)
                qv[i] = *(const float4*)(Qs + (ty * 4 + i) * LDPAD + d4 * 4);
#pragma unroll
            for (int j = 0; j < 4; j++)
                kv[j] = *(const float4*)(Ks + (tx * 4 + j) * LDPAD + d4 * 4);
#pragma unroll
            for (int i = 0; i < 4; i++)
#pragma unroll
                for (int j = 0; j < 4; j++)
                    s[i][j] += qv[i].x * kv[j].x + qv[i].y * kv[j].y +
                               qv[i].z * kv[j].z + qv[i].w * kv[j].w;
        }
        __syncthreads();  // all threads done reading Ks before P overwrite

        // online softmax per query row (row spread over 16 tx lanes)
#pragma unroll
        for (int i = 0; i < 4; i++) {
            float tmax = s[i][0];
#pragma unroll
            for (int j = 1; j < 4; j++) tmax = fmaxf(tmax, s[i][j]);
            tmax *= 0.125f;  // 1/sqrt(64) on the max too (scale whole row)
#pragma unroll
            for (int j = 0; j < 4; j++) s[i][j] *= 0.125f;
#pragma unroll
            for (int d = 8; d; d >>= 1)
                tmax = fmaxf(tmax, __shfl_xor_sync(0xffffffffu, tmax, d));
            float mnew = fmaxf(mr[i], tmax);
            float corr = __expf(mr[i] - mnew);
            mr[i] = mnew;
            float rs = 0.f;
#pragma unroll
            for (int j = 0; j < 4; j++) {
                float p = __expf(s[i][j] - mnew);
                s[i][j] = p;
                rs += p;
            }
#pragma unroll
            for (int d = 8; d; d >>= 1) rs += __shfl_xor_sync(0xffffffffu, rs, d);
            lsum[i] = lsum[i] * corr + rs;
#pragma unroll
            for (int j = 0; j < 4; j++) o[i][j] *= corr;
        }

        // write P into Ks storage
#pragma unroll
        for (int i = 0; i < 4; i++)
            *(float4*)(Ks + (ty * 4 + i) * LDPAD + tx * 4) =
                make_float4(s[i][0], s[i][1], s[i][2], s[i][3]);
        __syncthreads();

        // O += P @ V
#pragma unroll
        for (int s4 = 0; s4 < 16; s4++) {
            float4 pv[4], vv[4];
#pragma unroll
            for (int i = 0; i < 4; i++)
                pv[i] = *(const float4*)(Ks + (ty * 4 + i) * LDPAD + s4 * 4);
#pragma unroll
            for (int kk = 0; kk < 4; kk++)
                vv[kk] = *(const float4*)(Vs + (s4 * 4 + kk) * LDPAD + tx * 4);
#pragma unroll
            for (int i = 0; i < 4; i++) {
                o[i][0] += pv[i].x * vv[0].x + pv[i].y * vv[1].x +
                           pv[i].z * vv[2].x + pv[i].w * vv[3].x;
                o[i][1] += pv[i].x * vv[0].y + pv[i].y * vv[1].y +
                           pv[i].z * vv[2].y + pv[i].w * vv[3].y;
                o[i][2] += pv[i].x * vv[0].z + pv[i].y * vv[1].z +
                           pv[i].z * vv[2].z + pv[i].w * vv[3].z;
                o[i][3] += pv[i].x * vv[0].w + pv[i].y * vv[1].w +
                           pv[i].z * vv[2].w + pv[i].w * vv[3].w;
            }
        }
    }

#pragma unroll
    for (int i = 0; i < 4; i++) {
        float inv = 1.f / lsum[i];
        *(float4*)(ctx + (size_t)(t0 + ty * 4 + i) * ROWSTR + base + tx * 4) =
            make_float4(o[i][0] * inv, o[i][1] * inv, o[i][2] * inv, o[i][3] * inv);
    }
}

// ===========================================================================
// Fused residual-add + LayerNorm over rows of 1024. One block per row.
// out = (x - mean) * rsqrt(var + 1e-5) * g + beta,  x = a + res
// ===========================================================================
__global__ __launch_bounds__(256)
void add_ln_kernel(const float* __restrict__ a, const float* __restrict__ res,
                   const float* __restrict__ gma, const float* __restrict__ bta,
                   float* __restrict__ out) {
    __shared__ float red[16];
    const int row = blockIdx.x;
    const int tid = threadIdx.x;

    float4 va = *(const float4*)(a + (size_t)row * DIM + tid * 4);
    float4 vr = *(const float4*)(res + (size_t)row * DIM + tid * 4);
    float4 x;
    x.x = va.x + vr.x; x.y = va.y + vr.y; x.z = va.z + vr.z; x.w = va.w + vr.w;

    float sum = x.x + x.y + x.z + x.w;
    float sq = x.x * x.x + x.y * x.y + x.z * x.z + x.w * x.w;
#pragma unroll
    for (int d = 16; d; d >>= 1) {
        sum += __shfl_xor_sync(0xffffffffu, sum, d);
        sq += __shfl_xor_sync(0xffffffffu, sq, d);
    }
    const int warp = tid >> 5;
    if ((tid & 31) == 0) { red[warp] = sum; red[8 + warp] = sq; }
    __syncthreads();
    if (tid < 32) {
        float s = (tid < 8) ? red[tid] : 0.f;
        float q2 = (tid < 8) ? red[8 + tid] : 0.f;
#pragma unroll
        for (int d = 4; d; d >>= 1) {
            s += __shfl_xor_sync(0xffffffffu, s, d);
            q2 += __shfl_xor_sync(0xffffffffu, q2, d);
        }
        if (tid == 0) { red[0] = s; red[1] = q2; }
    }
    __syncthreads();
    const float mean = red[0] * (1.f / DIM);
    const float var = red[1] * (1.f / DIM) - mean * mean;
    const float rstd = rsqrtf(var + 1e-5f);

    float4 g4 = *(const float4*)(gma + tid * 4);
    float4 b4 = *(const float4*)(bta + tid * 4);
    float4 o;
    o.x = (x.x - mean) * rstd * g4.x + b4.x;
    o.y = (x.y - mean) * rstd * g4.y + b4.y;
    o.z = (x.z - mean) * rstd * g4.z + b4.z;
    o.w = (x.w - mean) * rstd * g4.w + b4.w;
    *(float4*)(out + (size_t)row * DIM + tid * 4) = o;
}

// ===========================================================================
// launch
// ===========================================================================
extern "C" void kernel_launch(void* const* d_in, const int* in_sizes, int n_in,
                              void* d_out, int out_size) {
    const float* x  = (const float*)d_in[0];
    const float* Wq = (const float*)d_in[1];
    const float* bq = (const float*)d_in[2];
    const float* Wk = (const float*)d_in[3];
    const float* bk = (const float*)d_in[4];
    const float* Wv = (const float*)d_in[5];
    const float* bv = (const float*)d_in[6];
    const float* Wo = (const float*)d_in[7];
    const float* bo = (const float*)d_in[8];
    const float* Wl = (const float*)d_in[9];
    const float* bl = (const float*)d_in[10];
    const float* g1 = (const float*)d_in[11];
    const float* b1 = (const float*)d_in[12];
    const float* g2 = (const float*)d_in[13];
    const float* b2 = (const float*)d_in[14];
    float* out = (float*)d_out;

    float *q, *k, *v, *ctx, *t1, *hh, *t2;
    cudaGetSymbolAddress((void**)&q, g_q);
    cudaGetSymbolAddress((void**)&k, g_k);
    cudaGetSymbolAddress((void**)&v, g_v);
    cudaGetSymbolAddress((void**)&ctx, g_ctx);
    cudaGetSymbolAddress((void**)&t1, g_t1);
    cudaGetSymbolAddress((void**)&hh, g_h);
    cudaGetSymbolAddress((void**)&t2, g_t2);

    cudaFuncSetAttribute(attn_kernel,
                         cudaFuncAttributeMaxDynamicSharedMemorySize, ATT_SMEM);

    dim3 ggrid(DIM / 128, NTOK / 128);  // (8, 32)
    dim3 gblk(256);

    gemm_nt_bias<<<ggrid, gblk>>>(x, Wq, bq, q);
    gemm_nt_bias<<<ggrid, gblk>>>(x, Wk, bk, k);
    gemm_nt_bias<<<ggrid, gblk>>>(x, Wv, bv, v);
    attn_kernel<<<dim3(BB * NH, TT / 64), 256, ATT_SMEM>>>(q, k, v, ctx);
    gemm_nt_bias<<<ggrid, gblk>>>(ctx, Wo, bo, t1);
    add_ln_kernel<<<NTOK, 256>>>(t1, x, g1, b1, hh);
    gemm_nt_bias<<<ggrid, gblk>>>(hh, Wl, bl, t2);
    add_ln_kernel<<<NTOK, 256>>>(t2, hh, g2, b2, out);
}

// round 4
// speedup vs baseline: 1.8728x; 1.8728x over previous
#include <cuda_runtime.h>
#include <cuda_bf16.h>
#include <cstdint>

#define TT 1024
#define BB 4
#define DIM 1024
#define NH 16
#define HD 64
#define NTOK (TT * BB)     // 4096 tokens
#define ROWSTR (BB * DIM)  // 4096 floats per t-step

// ---------------- scratch (device globals; no allocations allowed) --------
__device__ float g_q[NTOK * DIM];
__device__ float g_k[NTOK * DIM];
__device__ float g_v[NTOK * DIM];
__device__ float g_ctx[NTOK * DIM];
__device__ float g_t1[NTOK * DIM];
__device__ float g_h[NTOK * DIM];
__device__ float g_t2[NTOK * DIM];

// ===========================================================================
// GEMM via warp-level mma.sync (bf16, 2-term split, 3 passes => ~1e-5 rel err)
// C[4096,1024] = A[4096,1024] @ W[1024,1024]^T + bias
// Block tile 128x128, BK=32, 256 threads (8 warps: 2x4), double-buffered smem.
// smem rows padded to 40 bf16 (80B = 20 words) -> <=2-way conflict frag loads.
// ===========================================================================
#define PADK 40
#define TILEB (128 * PADK * 2)   // 10240 B, one 128x32 bf16 tile (padded)
#define STAGEB (4 * TILEB)       // Ah, Al, Bh, Bl
#define GEMM_SMEM (2 * STAGEB)   // 81920 B

__device__ __forceinline__ void mma16816(float* c, const uint32_t* a,
                                         const uint32_t* b) {
    asm volatile(
        "mma.sync.aligned.m16n8k16.row.col.f32.bf16.bf16.f32 "
        "{%0,%1,%2,%3}, {%4,%5,%6,%7}, {%8,%9}, {%0,%1,%2,%3};"
        : "+f"(c[0]), "+f"(c[1]), "+f"(c[2]), "+f"(c[3])
        : "r"(a[0]), "r"(a[1]), "r"(a[2]), "r"(a[3]), "r"(b[0]), "r"(b[1]));
}

__device__ __forceinline__ uint32_t pack_hi(float v0, float v1, float& l0,
                                            float& l1) {
    __nv_bfloat16 h0 = __float2bfloat16_rn(v0);
    __nv_bfloat16 h1 = __float2bfloat16_rn(v1);
    l0 = v0 - __bfloat162float(h0);
    l1 = v1 - __bfloat162float(h1);
    __nv_bfloat162 p;
    p.x = h0; p.y = h1;
    return *(uint32_t*)&p;
}

__device__ __forceinline__ uint32_t pack_lo(float l0, float l1) {
    __nv_bfloat162 p;
    p.x = __float2bfloat16_rn(l0);
    p.y = __float2bfloat16_rn(l1);
    return *(uint32_t*)&p;
}

__global__ __launch_bounds__(256, 1)
void gemm_mma(const float* __restrict__ A, const float* __restrict__ W,
              const float* __restrict__ bias, float* __restrict__ C) {
    extern __shared__ char sm[];
    const int tid = threadIdx.x;
    const int wid = tid >> 5;
    const int lane = tid & 31;
    const int laneR = lane >> 2;
    const int laneC = lane & 3;
    const int wm = wid >> 2;       // 0..1
    const int wn = wid & 3;        // 0..3
    const int mBase = wm * 64;
    const int nBase = wn * 32;
    const int m0 = blockIdx.y * 128;
    const int n0 = blockIdx.x * 128;

    // loader geometry: idx = tid + it*256; row = idx>>3 (0..127), c4 = (idx&7)*4
    const int lrow = tid >> 3;
    const int lc4 = (tid & 7) << 2;

    float acc[4][4][4];
#pragma unroll
    for (int i = 0; i < 4; i++)
#pragma unroll
        for (int j = 0; j < 4; j++)
#pragma unroll
            for (int r = 0; r < 4; r++) acc[i][j][r] = 0.f;

    float4 ra[4], rb[4];

    auto load_g = [&](int ch) {
        const int k0 = ch * 32;
#pragma unroll
        for (int it = 0; it < 4; it++) {
            int row = lrow + it * 32;
            ra[it] = *(const float4*)(A + (size_t)(m0 + row) * DIM + k0 + lc4);
            rb[it] = *(const float4*)(W + (size_t)(n0 + row) * DIM + k0 + lc4);
        }
    };

    auto cvt_store = [&](int b) {
        char* st = sm + b * STAGEB;
#pragma unroll
        for (int it = 0; it < 4; it++) {
            int row = lrow + it * 32;
            uint32_t boff = row * 80 + lc4 * 2;
            float l0, l1, l2, l3;
            uint2 uh, ul;
            uh.x = pack_hi(ra[it].x, ra[it].y, l0, l1);
            uh.y = pack_hi(ra[it].z, ra[it].w, l2, l3);
            ul.x = pack_lo(l0, l1);
            ul.y = pack_lo(l2, l3);
            *(uint2*)(st + boff) = uh;                 // Ah
            *(uint2*)(st + TILEB + boff) = ul;         // Al
            uh.x = pack_hi(rb[it].x, rb[it].y, l0, l1);
            uh.y = pack_hi(rb[it].z, rb[it].w, l2, l3);
            ul.x = pack_lo(l0, l1);
            ul.y = pack_lo(l2, l3);
            *(uint2*)(st + 2 * TILEB + boff) = uh;     // Bh
            *(uint2*)(st + 3 * TILEB + boff) = ul;     // Bl
        }
    };

    auto mma_stage = [&](int b) {
        const char* sb = sm + b * STAGEB;
#pragma unroll
        for (int s = 0; s < 2; s++) {
            const uint32_t so = s * 32 + laneC * 4;
            uint32_t bh[4][2], bl[4][2];
#pragma unroll
            for (int tj = 0; tj < 4; tj++) {
                uint32_t r = (nBase + tj * 8 + laneR) * 80 + so;
                bh[tj][0] = *(const uint32_t*)(sb + 2 * TILEB + r);
                bh[tj][1] = *(const uint32_t*)(sb + 2 * TILEB + r + 16);
                bl[tj][0] = *(const uint32_t*)(sb + 3 * TILEB + r);
                bl[tj][1] = *(const uint32_t*)(sb + 3 * TILEB + r + 16);
            }
#pragma unroll
            for (int ti = 0; ti < 4; ti++) {
                uint32_t r = (mBase + ti * 16 + laneR) * 80 + so;
                uint32_t ah[4], al[4];
                ah[0] = *(const uint32_t*)(sb + r);
                ah[1] = *(const uint32_t*)(sb + r + 640);
                ah[2] = *(const uint32_t*)(sb + r + 16);
                ah[3] = *(const uint32_t*)(sb + r + 656);
                al[0] = *(const uint32_t*)(sb + TILEB + r);
                al[1] = *(const uint32_t*)(sb + TILEB + r + 640);
                al[2] = *(const uint32_t*)(sb + TILEB + r + 16);
                al[3] = *(const uint32_t*)(sb + TILEB + r + 656);
#pragma unroll
                for (int tj = 0; tj < 4; tj++) {
                    mma16816(acc[ti][tj], ah, bh[tj]);
                    mma16816(acc[ti][tj], ah, bl[tj]);
                    mma16816(acc[ti][tj], al, bh[tj]);
                }
            }
        }
    };

    load_g(0);
    cvt_store(0);
    __syncthreads();

    for (int ch = 0; ch < 32; ch++) {
        const int b = ch & 1;
        if (ch < 31) load_g(ch + 1);
        mma_stage(b);
        if (ch < 31) cvt_store(b ^ 1);
        __syncthreads();
    }

    // epilogue: add bias, write fp32
#pragma unroll
    for (int ti = 0; ti < 4; ti++) {
        const int row = m0 + mBase + ti * 16 + laneR;
#pragma unroll
        for (int tj = 0; tj < 4; tj++) {
            const int col = n0 + nBase + tj * 8 + laneC * 2;
            const float b0 = __ldg(bias + col);
            const float b1 = __ldg(bias + col + 1);
            float2 o0 = make_float2(acc[ti][tj][0] + b0, acc[ti][tj][1] + b1);
            float2 o1 = make_float2(acc[ti][tj][2] + b0, acc[ti][tj][3] + b1);
            *(float2*)(C + (size_t)row * DIM + col) = o0;
            *(float2*)(C + (size_t)(row + 8) * DIM + col) = o1;
        }
    }
}

// ===========================================================================
// Flash-style full attention, fp32.
// Change vs R1: key micro-mapping strided (tx + 16j) -> conflict-free kv loads.
// ===========================================================================
#define LDPAD 68
#define ATT_SMEM (3 * 64 * LDPAD * 4)

__global__ __launch_bounds__(256, 2)
void attn_kernel(const float* __restrict__ q, const float* __restrict__ k,
                 const float* __restrict__ v, float* __restrict__ ctx) {
    extern __shared__ float smf[];
    float* Qs = smf;
    float* Ks = smf + 64 * LDPAD;      // reused for P
    float* Vs = smf + 2 * 64 * LDPAD;

    const int tid = threadIdx.x;
    const int tx = tid & 15;
    const int ty = tid >> 4;
    const int b = blockIdx.x >> 4;
    const int h = blockIdx.x & 15;
    const int t0 = blockIdx.y * 64;
    const size_t base = (size_t)b * DIM + h * HD;

#pragma unroll
    for (int i = 0; i < 4; i++) {
        int idx = tid + i * 256;
        int r = idx >> 4, c = (idx & 15) << 2;
        *(float4*)(Qs + r * LDPAD + c) =
            *(const float4*)(q + (size_t)(t0 + r) * ROWSTR + base + c);
    }

    float o[4][4];
#pragma unroll
    for (int i = 0; i < 4; i++)
#pragma unroll
        for (int j = 0; j < 4; j++) o[i][j] = 0.f;
    float mr[4] = {-1e30f, -1e30f, -1e30f, -1e30f};
    float lsum[4] = {0.f, 0.f, 0.f, 0.f};

    for (int s0 = 0; s0 < TT; s0 += 64) {
        __syncthreads();
#pragma unroll
        for (int i = 0; i < 4; i++) {
            int idx = tid + i * 256;
            int r = idx >> 4, c = (idx & 15) << 2;
            *(float4*)(Ks + r * LDPAD + c) =
                *(const float4*)(k + (size_t)(s0 + r) * ROWSTR + base + c);
            *(float4*)(Vs + r * LDPAD + c) =
                *(const float4*)(v + (size_t)(s0 + r) * ROWSTR + base + c);
        }
        __syncthreads();

        // S = Q K^T; thread handles keys {tx + 16j} (strided -> no conflicts)
        float s[4][4];
#pragma unroll
        for (int i = 0; i < 4; i++)
#pragma unroll
            for (int j = 0; j < 4; j++) s[i][j] = 0.f;
#pragma unroll
        for (int d4 = 0; d4 < 16; d4++) {
            float4 qv[4], kv[4];
#pragma unroll
            for (int i = 0; i < 4; i++)
                qv[i] = *(const float4*)(Qs + (ty * 4 + i) * LDPAD + d4 * 4);
#pragma unroll
            for (int j = 0; j < 4; j++)
                kv[j] = *(const float4*)(Ks + (tx + 16 * j) * LDPAD + d4 * 4);
#pragma unroll
            for (int i = 0; i < 4; i++)
#pragma unroll
                for (int j = 0; j < 4; j++)
                    s[i][j] += qv[i].x * kv[j].x + qv[i].y * kv[j].y +
                               qv[i].z * kv[j].z + qv[i].w * kv[j].w;
        }
        __syncthreads();  // done reading Ks before P overwrite

        // online softmax (16 tx lanes per query row; keys {tx+16j} cover all 64)
#pragma unroll
        for (int i = 0; i < 4; i++) {
            float tmax = s[i][0];
#pragma unroll
            for (int j = 1; j < 4; j++) tmax = fmaxf(tmax, s[i][j]);
            tmax *= 0.125f;
#pragma unroll
            for (int j = 0; j < 4; j++) s[i][j] *= 0.125f;
#pragma unroll
            for (int d = 8; d; d >>= 1)
                tmax = fmaxf(tmax, __shfl_xor_sync(0xffffffffu, tmax, d));
            float mnew = fmaxf(mr[i], tmax);
            float corr = __expf(mr[i] - mnew);
            mr[i] = mnew;
            float rs = 0.f;
#pragma unroll
            for (int j = 0; j < 4; j++) {
                float p = __expf(s[i][j] - mnew);
                s[i][j] = p;
                rs += p;
            }
#pragma unroll
            for (int d = 8; d; d >>= 1) rs += __shfl_xor_sync(0xffffffffu, rs, d);
            lsum[i] = lsum[i] * corr + rs;
#pragma unroll
            for (int j = 0; j < 4; j++) o[i][j] *= corr;
        }

        // write P (scattered scalar stores: row q, col tx+16j)
#pragma unroll
        for (int i = 0; i < 4; i++)
#pragma unroll
            for (int j = 0; j < 4; j++)
                Ks[(ty * 4 + i) * LDPAD + tx + 16 * j] = s[i][j];
        __syncthreads();

        // O += P @ V (unchanged: pv broadcast, vv contiguous)
#pragma unroll
        for (int s4 = 0; s4 < 16; s4++) {
            float4 pv[4], vv[4];
#pragma unroll
            for (int i = 0; i < 4; i++)
                pv[i] = *(const float4*)(Ks + (ty * 4 + i) * LDPAD + s4 * 4);
#pragma unroll
            for (int kk = 0; kk < 4; kk++)
                vv[kk] = *(const float4*)(Vs + (s4 * 4 + kk) * LDPAD + tx * 4);
#pragma unroll
            for (int i = 0; i < 4; i++) {
                o[i][0] += pv[i].x * vv[0].x + pv[i].y * vv[1].x +
                           pv[i].z * vv[2].x + pv[i].w * vv[3].x;
                o[i][1] += pv[i].x * vv[0].y + pv[i].y * vv[1].y +
                           pv[i].z * vv[2].y + pv[i].w * vv[3].y;
                o[i][2] += pv[i].x * vv[0].z + pv[i].y * vv[1].z +
                           pv[i].z * vv[2].z + pv[i].w * vv[3].z;
                o[i][3] += pv[i].x * vv[0].w + pv[i].y * vv[1].w +
                           pv[i].z * vv[2].w + pv[i].w * vv[3].w;
            }
        }
    }

#pragma unroll
    for (int i = 0; i < 4; i++) {
        float inv = 1.f / lsum[i];
        *(float4*)(ctx + (size_t)(t0 + ty * 4 + i) * ROWSTR + base + tx * 4) =
            make_float4(o[i][0] * inv, o[i][1] * inv, o[i][2] * inv, o[i][3] * inv);
    }
}

// ===========================================================================
// Fused residual-add + LayerNorm over rows of 1024. One block per row.
// ===========================================================================
__global__ __launch_bounds__(256)
void add_ln_kernel(const float* __restrict__ a, const float* __restrict__ res,
                   const float* __restrict__ gma, const float* __restrict__ bta,
                   float* __restrict__ out) {
    __shared__ float red[16];
    const int row = blockIdx.x;
    const int tid = threadIdx.x;

    float4 va = *(const float4*)(a + (size_t)row * DIM + tid * 4);
    float4 vr = *(const float4*)(res + (size_t)row * DIM + tid * 4);
    float4 x;
    x.x = va.x + vr.x; x.y = va.y + vr.y; x.z = va.z + vr.z; x.w = va.w + vr.w;

    float sum = x.x + x.y + x.z + x.w;
    float sq = x.x * x.x + x.y * x.y + x.z * x.z + x.w * x.w;
#pragma unroll
    for (int d = 16; d; d >>= 1) {
        sum += __shfl_xor_sync(0xffffffffu, sum, d);
        sq += __shfl_xor_sync(0xffffffffu, sq, d);
    }
    const int warp = tid >> 5;
    if ((tid & 31) == 0) { red[warp] = sum; red[8 + warp] = sq; }
    __syncthreads();
    if (tid < 32) {
        float s = (tid < 8) ? red[tid] : 0.f;
        float q2 = (tid < 8) ? red[8 + tid] : 0.f;
#pragma unroll
        for (int d = 4; d; d >>= 1) {
            s += __shfl_xor_sync(0xffffffffu, s, d);
            q2 += __shfl_xor_sync(0xffffffffu, q2, d);
        }
        if (tid == 0) { red[0] = s; red[1] = q2; }
    }
    __syncthreads();
    const float mean = red[0] * (1.f / DIM);
    const float var = red[1] * (1.f / DIM) - mean * mean;
    const float rstd = rsqrtf(var + 1e-5f);

    float4 g4 = *(const float4*)(gma + tid * 4);
    float4 b4 = *(const float4*)(bta + tid * 4);
    float4 o;
    o.x = (x.x - mean) * rstd * g4.x + b4.x;
    o.y = (x.y - mean) * rstd * g4.y + b4.y;
    o.z = (x.z - mean) * rstd * g4.z + b4.z;
    o.w = (x.w - mean) * rstd * g4.w + b4.w;
    *(float4*)(out + (size_t)row * DIM + tid * 4) = o;
}

// ===========================================================================
// launch
// ===========================================================================
extern "C" void kernel_launch(void* const* d_in, const int* in_sizes, int n_in,
                              void* d_out, int out_size) {
    const float* x  = (const float*)d_in[0];
    const float* Wq = (const float*)d_in[1];
    const float* bq = (const float*)d_in[2];
    const float* Wk = (const float*)d_in[3];
    const float* bk = (const float*)d_in[4];
    const float* Wv = (const float*)d_in[5];
    const float* bv = (const float*)d_in[6];
    const float* Wo = (const float*)d_in[7];
    const float* bo = (const float*)d_in[8];
    const float* Wl = (const float*)d_in[9];
    const float* bl = (const float*)d_in[10];
    const float* g1 = (const float*)d_in[11];
    const float* b1 = (const float*)d_in[12];
    const float* g2 = (const float*)d_in[13];
    const float* b2 = (const float*)d_in[14];
    float* out = (float*)d_out;

    float *q, *k, *v, *ctx, *t1, *hh, *t2;
    cudaGetSymbolAddress((void**)&q, g_q);
    cudaGetSymbolAddress((void**)&k, g_k);
    cudaGetSymbolAddress((void**)&v, g_v);
    cudaGetSymbolAddress((void**)&ctx, g_ctx);
    cudaGetSymbolAddress((void**)&t1, g_t1);
    cudaGetSymbolAddress((void**)&hh, g_h);
    cudaGetSymbolAddress((void**)&t2, g_t2);

    cudaFuncSetAttribute(attn_kernel,
                         cudaFuncAttributeMaxDynamicSharedMemorySize, ATT_SMEM);
    cudaFuncSetAttribute(gemm_mma,
                         cudaFuncAttributeMaxDynamicSharedMemorySize, GEMM_SMEM);

    dim3 ggrid(DIM / 128, NTOK / 128);  // (8, 32)
    dim3 gblk(256);

    gemm_mma<<<ggrid, gblk, GEMM_SMEM>>>(x, Wq, bq, q);
    gemm_mma<<<ggrid, gblk, GEMM_SMEM>>>(x, Wk, bk, k);
    gemm_mma<<<ggrid, gblk, GEMM_SMEM>>>(x, Wv, bv, v);
    attn_kernel<<<dim3(BB * NH, TT / 64), 256, ATT_SMEM>>>(q, k, v, ctx);
    gemm_mma<<<ggrid, gblk, GEMM_SMEM>>>(ctx, Wo, bo, t1);
    add_ln_kernel<<<NTOK, 256>>>(t1, x, g1, b1, hh);
    gemm_mma<<<ggrid, gblk, GEMM_SMEM>>>(hh, Wl, bl, t2);
    add_ln_kernel<<<NTOK, 256>>>(t2, hh, g2, b2, out);
}

// round 7
// speedup vs baseline: 2.7130x; 1.4487x over previous
#include <cuda_runtime.h>
#include <cuda_bf16.h>
#include <cstdint>

#define TT 1024
#define BB 4
#define DIM 1024
#define NH 16
#define HD 64
#define NTOK (TT * BB)     // 4096 tokens
#define ROWSTR (BB * DIM)  // 4096 floats per t-step

// ---------------- scratch (device globals; no allocations allowed) --------
__device__ float g_q[NTOK * DIM];
__device__ float g_k[NTOK * DIM];
__device__ float g_v[NTOK * DIM];
__device__ float g_ctx[NTOK * DIM];
__device__ float g_t1[NTOK * DIM];
__device__ float g_h[NTOK * DIM];
__device__ float g_t2[NTOK * DIM];

// ===========================================================================
// common mma helpers
// ===========================================================================
__device__ __forceinline__ void mma16816(float* c, const uint32_t* a,
                                         const uint32_t* b) {
    asm volatile(
        "mma.sync.aligned.m16n8k16.row.col.f32.bf16.bf16.f32 "
        "{%0,%1,%2,%3}, {%4,%5,%6,%7}, {%8,%9}, {%0,%1,%2,%3};"
        : "+f"(c[0]), "+f"(c[1]), "+f"(c[2]), "+f"(c[3])
        : "r"(a[0]), "r"(a[1]), "r"(a[2]), "r"(a[3]), "r"(b[0]), "r"(b[1]));
}

__device__ __forceinline__ uint32_t pack_hi(float v0, float v1, float& l0,
                                            float& l1) {
    __nv_bfloat16 h0 = __float2bfloat16_rn(v0);
    __nv_bfloat16 h1 = __float2bfloat16_rn(v1);
    l0 = v0 - __bfloat162float(h0);
    l1 = v1 - __bfloat162float(h1);
    __nv_bfloat162 p;
    p.x = h0; p.y = h1;
    return *(uint32_t*)&p;
}

__device__ __forceinline__ uint32_t pack_lo(float l0, float l1) {
    __nv_bfloat162 p;
    p.x = __float2bfloat16_rn(l0);
    p.y = __float2bfloat16_rn(l1);
    return *(uint32_t*)&p;
}

__device__ __forceinline__ uint32_t pack2(float v0, float v1) {
    __nv_bfloat162 p;
    p.x = __float2bfloat16_rn(v0);
    p.y = __float2bfloat16_rn(v1);
    return *(uint32_t*)&p;
}

// ===========================================================================
// GEMM via warp-level mma.sync (bf16, 2-term split, 3 passes => ~1e-5 rel err)
// C[4096,1024] = A @ W^T + bias. 128x128 tile, BK=32, 8 warps, double buffer.
// ===========================================================================
#define PADK 40
#define TILEB (128 * PADK * 2)
#define STAGEB (4 * TILEB)
#define GEMM_SMEM (2 * STAGEB)

struct GemmCore {
    const float* A; const float* W; const float* bias; float* C;
};

__device__ __forceinline__ void gemm_body(const float* __restrict__ A,
                                          const float* __restrict__ W,
                                          const float* __restrict__ bias,
                                          float* __restrict__ C, char* sm) {
    const int tid = threadIdx.x;
    const int wid = tid >> 5;
    const int lane = tid & 31;
    const int laneR = lane >> 2;
    const int laneC = lane & 3;
    const int wm = wid >> 2;
    const int wn = wid & 3;
    const int mBase = wm * 64;
    const int nBase = wn * 32;
    const int m0 = blockIdx.y * 128;
    const int n0 = blockIdx.x * 128;

    const int lrow = tid >> 3;
    const int lc4 = (tid & 7) << 2;

    float acc[4][4][4];
#pragma unroll
    for (int i = 0; i < 4; i++)
#pragma unroll
        for (int j = 0; j < 4; j++)
#pragma unroll
            for (int r = 0; r < 4; r++) acc[i][j][r] = 0.f;

    float4 ra[4], rb[4];

    auto load_g = [&](int ch) {
        const int k0 = ch * 32;
#pragma unroll
        for (int it = 0; it < 4; it++) {
            int row = lrow + it * 32;
            ra[it] = *(const float4*)(A + (size_t)(m0 + row) * DIM + k0 + lc4);
            rb[it] = *(const float4*)(W + (size_t)(n0 + row) * DIM + k0 + lc4);
        }
    };

    auto cvt_store = [&](int b) {
        char* st = sm + b * STAGEB;
#pragma unroll
        for (int it = 0; it < 4; it++) {
            int row = lrow + it * 32;
            uint32_t boff = row * 80 + lc4 * 2;
            float l0, l1, l2, l3;
            uint2 uh, ul;
            uh.x = pack_hi(ra[it].x, ra[it].y, l0, l1);
            uh.y = pack_hi(ra[it].z, ra[it].w, l2, l3);
            ul.x = pack2(l0, l1);
            ul.y = pack2(l2, l3);
            *(uint2*)(st + boff) = uh;
            *(uint2*)(st + TILEB + boff) = ul;
            uh.x = pack_hi(rb[it].x, rb[it].y, l0, l1);
            uh.y = pack_hi(rb[it].z, rb[it].w, l2, l3);
            ul.x = pack2(l0, l1);
            ul.y = pack2(l2, l3);
            *(uint2*)(st + 2 * TILEB + boff) = uh;
            *(uint2*)(st + 3 * TILEB + boff) = ul;
        }
    };

    auto mma_stage = [&](int b) {
        const char* sb = sm + b * STAGEB;
#pragma unroll
        for (int s = 0; s < 2; s++) {
            const uint32_t so = s * 32 + laneC * 4;
            uint32_t bh[4][2], bl[4][2];
#pragma unroll
            for (int tj = 0; tj < 4; tj++) {
                uint32_t r = (nBase + tj * 8 + laneR) * 80 + so;
                bh[tj][0] = *(const uint32_t*)(sb + 2 * TILEB + r);
                bh[tj][1] = *(const uint32_t*)(sb + 2 * TILEB + r + 16);
                bl[tj][0] = *(const uint32_t*)(sb + 3 * TILEB + r);
                bl[tj][1] = *(const uint32_t*)(sb + 3 * TILEB + r + 16);
            }
#pragma unroll
            for (int ti = 0; ti < 4; ti++) {
                uint32_t r = (mBase + ti * 16 + laneR) * 80 + so;
                uint32_t ah[4], al[4];
                ah[0] = *(const uint32_t*)(sb + r);
                ah[1] = *(const uint32_t*)(sb + r + 640);
                ah[2] = *(const uint32_t*)(sb + r + 16);
                ah[3] = *(const uint32_t*)(sb + r + 656);
                al[0] = *(const uint32_t*)(sb + TILEB + r);
                al[1] = *(const uint32_t*)(sb + TILEB + r + 640);
                al[2] = *(const uint32_t*)(sb + TILEB + r + 16);
                al[3] = *(const uint32_t*)(sb + TILEB + r + 656);
#pragma unroll
                for (int tj = 0; tj < 4; tj++) {
                    mma16816(acc[ti][tj], ah, bh[tj]);
                    mma16816(acc[ti][tj], ah, bl[tj]);
                    mma16816(acc[ti][tj], al, bh[tj]);
                }
            }
        }
    };

    load_g(0);
    cvt_store(0);
    __syncthreads();

    for (int ch = 0; ch < 32; ch++) {
        const int b = ch & 1;
        if (ch < 31) load_g(ch + 1);
        mma_stage(b);
        if (ch < 31) cvt_store(b ^ 1);
        __syncthreads();
    }

#pragma unroll
    for (int ti = 0; ti < 4; ti++) {
        const int row = m0 + mBase + ti * 16 + laneR;
#pragma unroll
        for (int tj = 0; tj < 4; tj++) {
            const int col = n0 + nBase + tj * 8 + laneC * 2;
            const float b0 = __ldg(bias + col);
            const float b1 = __ldg(bias + col + 1);
            float2 o0 = make_float2(acc[ti][tj][0] + b0, acc[ti][tj][1] + b1);
            float2 o1 = make_float2(acc[ti][tj][2] + b0, acc[ti][tj][3] + b1);
            *(float2*)(C + (size_t)row * DIM + col) = o0;
            *(float2*)(C + (size_t)(row + 8) * DIM + col) = o1;
        }
    }
}

__global__ __launch_bounds__(256, 1)
void gemm_mma(const float* __restrict__ A, const float* __restrict__ W,
              const float* __restrict__ bias, float* __restrict__ C) {
    extern __shared__ char sm[];
    gemm_body(A, W, bias, C, sm);
}

// batched QKV: grid.z picks (W,b,out); same A. Fills the wave tail.
__global__ __launch_bounds__(256, 1)
void gemm_mma_qkv(const float* __restrict__ A,
                  const float* __restrict__ W0, const float* __restrict__ b0,
                  float* __restrict__ C0,
                  const float* __restrict__ W1, const float* __restrict__ b1,
                  float* __restrict__ C1,
                  const float* __restrict__ W2, const float* __restrict__ b2,
                  float* __restrict__ C2) {
    extern __shared__ char sm[];
    const float* W = (blockIdx.z == 0) ? W0 : (blockIdx.z == 1) ? W1 : W2;
    const float* b = (blockIdx.z == 0) ? b0 : (blockIdx.z == 1) ? b1 : b2;
    float* C = (blockIdx.z == 0) ? C0 : (blockIdx.z == 1) ? C1 : C2;
    gemm_body(A, W, b, C, sm);
}

// ===========================================================================
// Attention via mma.sync bf16 split (FA2-style, P stays in registers).
// Block: one (b,h), 128 query rows. 8 warps; warp w owns rows w*16..w*16+15.
// K/V processed in 128-key tiles; 3-pass split on both QK^T and P@V.
// smem: Qh/Ql/Kh/Kl [128][72 bf16] (144B rows), Vt h/l [64][138 bf16] (276B).
// ===========================================================================
#define SQH 0
#define SQL 18432
#define SKH 36864
#define SKL 55296
#define SVH 73728
#define SVL 91392
#define ATT_SMEM 109056
#define QKSTR 144     // bytes per Q/K row
#define VTSTR 276     // bytes per Vt row

__global__ __launch_bounds__(256, 1)
void attn_mma_kernel(const float* __restrict__ q, const float* __restrict__ k,
                     const float* __restrict__ v, float* __restrict__ ctx) {
    extern __shared__ char smc[];
    const int tid = threadIdx.x;
    const int wid = tid >> 5;
    const int lane = tid & 31;
    const int laneR = lane >> 2;
    const int laneC = lane & 3;
    const int bh = blockIdx.x;
    const int b = bh >> 4;
    const int h = bh & 15;
    const int t0 = blockIdx.y * 128;
    const size_t base = (size_t)b * DIM + h * HD;
    const int mrow = wid * 16;

    // ---- load Q tile (128x64), split into Qh/Ql ----
#pragma unroll
    for (int it = 0; it < 8; it++) {
        int task = tid + it * 256;
        int row = task >> 4;
        int c = (task & 15) << 2;
        float4 f = *(const float4*)(q + (size_t)(t0 + row) * ROWSTR + base + c);
        float l0, l1, l2, l3;
        uint2 uh, ul;
        uh.x = pack_hi(f.x, f.y, l0, l1);
        uh.y = pack_hi(f.z, f.w, l2, l3);
        ul.x = pack2(l0, l1);
        ul.y = pack2(l2, l3);
        *(uint2*)(smc + SQH + row * QKSTR + c * 2) = uh;
        *(uint2*)(smc + SQL + row * QKSTR + c * 2) = ul;
    }

    float oacc[8][4];
#pragma unroll
    for (int i = 0; i < 8; i++)
#pragma unroll
        for (int r = 0; r < 4; r++) oacc[i][r] = 0.f;
    float mr[2] = {-1e30f, -1e30f};
    float ls[2] = {0.f, 0.f};

    for (int kt = 0; kt < 8; kt++) {
        const int s0 = kt * 128;
        __syncthreads();  // previous tile's smem reads done

        // ---- load K tile (128x64) split ----
#pragma unroll
        for (int it = 0; it < 8; it++) {
            int task = tid + it * 256;
            int row = task >> 4;
            int c = (task & 15) << 2;
            float4 f = *(const float4*)(k + (size_t)(s0 + row) * ROWSTR + base + c);
            float l0, l1, l2, l3;
            uint2 uh, ul;
            uh.x = pack_hi(f.x, f.y, l0, l1);
            uh.y = pack_hi(f.z, f.w, l2, l3);
            ul.x = pack2(l0, l1);
            ul.y = pack2(l2, l3);
            *(uint2*)(smc + SKH + row * QKSTR + c * 2) = uh;
            *(uint2*)(smc + SKL + row * QKSTR + c * 2) = ul;
        }

        // ---- load V tile transposed: Vt[d][s], s-pairs packed in u32 ----
#pragma unroll
        for (int it = 0; it < 4; it++) {
            int task = tid + it * 256;
            int sp = task >> 4;        // 0..63 key pair
            int d0 = (task & 15) << 2; // 0..60
            const float* vp = v + (size_t)(s0 + 2 * sp) * ROWSTR + base + d0;
            float4 f0 = *(const float4*)vp;
            float4 f1 = *(const float4*)(vp + ROWSTR);
            float a0[4] = {f0.x, f0.y, f0.z, f0.w};
            float a1[4] = {f1.x, f1.y, f1.z, f1.w};
#pragma unroll
            for (int e = 0; e < 4; e++) {
                float h0, h1, dummy0, dummy1;
                uint32_t uh = pack_hi(a0[e], a1[e], h0, h1);
                uint32_t ul = pack2(h0, h1);
                *(uint32_t*)(smc + SVH + (d0 + e) * VTSTR + sp * 4) = uh;
                *(uint32_t*)(smc + SVL + (d0 + e) * VTSTR + sp * 4) = ul;
                (void)dummy0; (void)dummy1;
            }
        }
        __syncthreads();

        // ---- S = Q K^T (warp: 16 rows x 128 keys), 3-pass split ----
        float sacc[16][4];
#pragma unroll
        for (int nt = 0; nt < 16; nt++)
#pragma unroll
            for (int r = 0; r < 4; r++) sacc[nt][r] = 0.f;

#pragma unroll
        for (int ks = 0; ks < 4; ks++) {
            const uint32_t qb = (mrow + laneR) * QKSTR + ks * 32 + laneC * 4;
            uint32_t ah[4], al[4];
            ah[0] = *(const uint32_t*)(smc + SQH + qb);
            ah[1] = *(const uint32_t*)(smc + SQH + qb + 8 * QKSTR);
            ah[2] = *(const uint32_t*)(smc + SQH + qb + 16);
            ah[3] = *(const uint32_t*)(smc + SQH + qb + 8 * QKSTR + 16);
            al[0] = *(const uint32_t*)(smc + SQL + qb);
            al[1] = *(const uint32_t*)(smc + SQL + qb + 8 * QKSTR);
            al[2] = *(const uint32_t*)(smc + SQL + qb + 16);
            al[3] = *(const uint32_t*)(smc + SQL + qb + 8 * QKSTR + 16);
#pragma unroll
            for (int nt = 0; nt < 16; nt++) {
                const uint32_t kb = (nt * 8 + laneR) * QKSTR + ks * 32 + laneC * 4;
                uint32_t bhf[2], blf[2];
                bhf[0] = *(const uint32_t*)(smc + SKH + kb);
                bhf[1] = *(const uint32_t*)(smc + SKH + kb + 16);
                blf[0] = *(const uint32_t*)(smc + SKL + kb);
                blf[1] = *(const uint32_t*)(smc + SKL + kb + 16);
                mma16816(sacc[nt], ah, bhf);
                mma16816(sacc[nt], ah, blf);
                mma16816(sacc[nt], al, bhf);
            }
        }

        // ---- online softmax on raw scores (scale 0.125 folded into exp) ----
#pragma unroll
        for (int r = 0; r < 2; r++) {
            float mt = -1e30f;
#pragma unroll
            for (int nt = 0; nt < 16; nt++)
                mt = fmaxf(mt, fmaxf(sacc[nt][2 * r], sacc[nt][2 * r + 1]));
            mt = fmaxf(mt, __shfl_xor_sync(0xffffffffu, mt, 1));
            mt = fmaxf(mt, __shfl_xor_sync(0xffffffffu, mt, 2));
            float mnew = fmaxf(mr[r], mt);
            float corr = __expf((mr[r] - mnew) * 0.125f);
            mr[r] = mnew;
            const float mm = mnew * 0.125f;
            float rs = 0.f;
#pragma unroll
            for (int nt = 0; nt < 16; nt++) {
                float p0 = __expf(fmaf(sacc[nt][2 * r], 0.125f, -mm));
                float p1 = __expf(fmaf(sacc[nt][2 * r + 1], 0.125f, -mm));
                sacc[nt][2 * r] = p0;
                sacc[nt][2 * r + 1] = p1;
                rs += p0 + p1;
            }
            rs += __shfl_xor_sync(0xffffffffu, rs, 1);
            rs += __shfl_xor_sync(0xffffffffu, rs, 2);
            ls[r] = ls[r] * corr + rs;
#pragma unroll
            for (int nt2 = 0; nt2 < 8; nt2++) {
                oacc[nt2][2 * r] *= corr;
                oacc[nt2][2 * r + 1] *= corr;
            }
        }

        // ---- O += P @ V, P from registers (split), V from Vt smem ----
#pragma unroll
        for (int j = 0; j < 8; j++) {
            uint32_t ph[4], pl[4];
            float l0, l1;
            ph[0] = pack_hi(sacc[2 * j][0], sacc[2 * j][1], l0, l1);
            pl[0] = pack2(l0, l1);
            ph[1] = pack_hi(sacc[2 * j][2], sacc[2 * j][3], l0, l1);
            pl[1] = pack2(l0, l1);
            ph[2] = pack_hi(sacc[2 * j + 1][0], sacc[2 * j + 1][1], l0, l1);
            pl[2] = pack2(l0, l1);
            ph[3] = pack_hi(sacc[2 * j + 1][2], sacc[2 * j + 1][3], l0, l1);
            pl[3] = pack2(l0, l1);
#pragma unroll
            for (int nt2 = 0; nt2 < 8; nt2++) {
                const uint32_t vb = (nt2 * 8 + laneR) * VTSTR + j * 32 + laneC * 4;
                uint32_t vh[2], vl[2];
                vh[0] = *(const uint32_t*)(smc + SVH + vb);
                vh[1] = *(const uint32_t*)(smc + SVH + vb + 16);
                vl[0] = *(const uint32_t*)(smc + SVL + vb);
                vl[1] = *(const uint32_t*)(smc + SVL + vb + 16);
                mma16816(oacc[nt2], ph, vh);
                mma16816(oacc[nt2], ph, vl);
                mma16816(oacc[nt2], pl, vh);
            }
        }
    }

    // ---- normalize and store ----
    const float inv0 = 1.f / ls[0];
    const float inv1 = 1.f / ls[1];
    const int r0 = t0 + mrow + laneR;
#pragma unroll
    for (int nt2 = 0; nt2 < 8; nt2++) {
        const size_t col = base + nt2 * 8 + laneC * 2;
        *(float2*)(ctx + (size_t)r0 * ROWSTR + col) =
            make_float2(oacc[nt2][0] * inv0, oacc[nt2][1] * inv0);
        *(float2*)(ctx + (size_t)(r0 + 8) * ROWSTR + col) =
            make_float2(oacc[nt2][2] * inv1, oacc[nt2][3] * inv1);
    }
}

// ===========================================================================
// Fused residual-add + LayerNorm over rows of 1024. One block per row.
// ===========================================================================
__global__ __launch_bounds__(256)
void add_ln_kernel(const float* __restrict__ a, const float* __restrict__ res,
                   const float* __restrict__ gma, const float* __restrict__ bta,
                   float* __restrict__ out) {
    __shared__ float red[16];
    const int row = blockIdx.x;
    const int tid = threadIdx.x;

    float4 va = *(const float4*)(a + (size_t)row * DIM + tid * 4);
    float4 vr = *(const float4*)(res + (size_t)row * DIM + tid * 4);
    float4 x;
    x.x = va.x + vr.x; x.y = va.y + vr.y; x.z = va.z + vr.z; x.w = va.w + vr.w;

    float sum = x.x + x.y + x.z + x.w;
    float sq = x.x * x.x + x.y * x.y + x.z * x.z + x.w * x.w;
#pragma unroll
    for (int d = 16; d; d >>= 1) {
        sum += __shfl_xor_sync(0xffffffffu, sum, d);
        sq += __shfl_xor_sync(0xffffffffu, sq, d);
    }
    const int warp = tid >> 5;
    if ((tid & 31) == 0) { red[warp] = sum; red[8 + warp] = sq; }
    __syncthreads();
    if (tid < 32) {
        float s = (tid < 8) ? red[tid] : 0.f;
        float q2 = (tid < 8) ? red[8 + tid] : 0.f;
#pragma unroll
        for (int d = 4; d; d >>= 1) {
            s += __shfl_xor_sync(0xffffffffu, s, d);
            q2 += __shfl_xor_sync(0xffffffffu, q2, d);
        }
        if (tid == 0) { red[0] = s; red[1] = q2; }
    }
    __syncthreads();
    const float mean = red[0] * (1.f / DIM);
    const float var = red[1] * (1.f / DIM) - mean * mean;
    const float rstd = rsqrtf(var + 1e-5f);

    float4 g4 = *(const float4*)(gma + tid * 4);
    float4 b4 = *(const float4*)(bta + tid * 4);
    float4 o;
    o.x = (x.x - mean) * rstd * g4.x + b4.x;
    o.y = (x.y - mean) * rstd * g4.y + b4.y;
    o.z = (x.z - mean) * rstd * g4.z + b4.z;
    o.w = (x.w - mean) * rstd * g4.w + b4.w;
    *(float4*)(out + (size_t)row * DIM + tid * 4) = o;
}

// ===========================================================================
// launch
// ===========================================================================
extern "C" void kernel_launch(void* const* d_in, const int* in_sizes, int n_in,
                              void* d_out, int out_size) {
    const float* x  = (const float*)d_in[0];
    const float* Wq = (const float*)d_in[1];
    const float* bq = (const float*)d_in[2];
    const float* Wk = (const float*)d_in[3];
    const float* bk = (const float*)d_in[4];
    const float* Wv = (const float*)d_in[5];
    const float* bv = (const float*)d_in[6];
    const float* Wo = (const float*)d_in[7];
    const float* bo = (const float*)d_in[8];
    const float* Wl = (const float*)d_in[9];
    const float* bl = (const float*)d_in[10];
    const float* g1 = (const float*)d_in[11];
    const float* b1 = (const float*)d_in[12];
    const float* g2 = (const float*)d_in[13];
    const float* b2 = (const float*)d_in[14];
    float* out = (float*)d_out;

    float *q, *k, *v, *ctx, *t1, *hh, *t2;
    cudaGetSymbolAddress((void**)&q, g_q);
    cudaGetSymbolAddress((void**)&k, g_k);
    cudaGetSymbolAddress((void**)&v, g_v);
    cudaGetSymbolAddress((void**)&ctx, g_ctx);
    cudaGetSymbolAddress((void**)&t1, g_t1);
    cudaGetSymbolAddress((void**)&hh, g_h);
    cudaGetSymbolAddress((void**)&t2, g_t2);

    cudaFuncSetAttribute(attn_mma_kernel,
                         cudaFuncAttributeMaxDynamicSharedMemorySize, ATT_SMEM);
    cudaFuncSetAttribute(gemm_mma,
                         cudaFuncAttributeMaxDynamicSharedMemorySize, GEMM_SMEM);
    cudaFuncSetAttribute(gemm_mma_qkv,
                         cudaFuncAttributeMaxDynamicSharedMemorySize, GEMM_SMEM);

    dim3 ggrid(DIM / 128, NTOK / 128);      // (8, 32)
    dim3 ggrid3(DIM / 128, NTOK / 128, 3);  // QKV batched
    dim3 gblk(256);

    gemm_mma_qkv<<<ggrid3, gblk, GEMM_SMEM>>>(x, Wq, bq, q, Wk, bk, k, Wv, bv, v);
    attn_mma_kernel<<<dim3(BB * NH, TT / 128), 256, ATT_SMEM>>>(q, k, v, ctx);
    gemm_mma<<<ggrid, gblk, GEMM_SMEM>>>(ctx, Wo, bo, t1);
    add_ln_kernel<<<NTOK, 256>>>(t1, x, g1, b1, hh);
    gemm_mma<<<ggrid, gblk, GEMM_SMEM>>>(hh, Wl, bl, t2);
    add_ln_kernel<<<NTOK, 256>>>(t2, hh, g2, b2, out);
}